// round 5
// baseline (speedup 1.0000x reference)
#include <cuda_runtime.h>
#include <cuda_bf16.h>
#include <cstdint>

// Problem constants
#define KC   1024
#define DD   64
#define BB   32
#define TT   2048
#define NV   (BB*TT)
#define QE   (BB*DD*TT)
#define DECAYF 0.99f
#define OMD    (1.0f - 0.99f)
#define COMMITF 0.25f
#define EPSF 1e-5f

// Output layout (flat float32, reference tuple order)
#define OFF_Q      0
#define OFF_LOSS   (OFF_Q + QE)
#define OFF_CODES  (OFF_LOSS + 1)
#define OFF_NEWEMB (OFF_CODES + NV)
#define OFF_NEWCS  (OFF_NEWEMB + KC*DD)
#define OFF_NEWW   (OFF_NEWCS + KC)

// Scratch (device globals — no allocation)
__device__ float g_hn[KC];
__device__ float g_counts[KC];
__device__ float g_dw[KC*DD];
__device__ float g_invcs[KC];
__device__ float g_loss;
__device__ __align__(256) uint16_t g_ehi[KC*DD];   // bf16 hi part of embedding
__device__ __align__(256) uint16_t g_elo[KC*DD];   // bf16 lo part

#define SWZ(o) ((o) ^ (((o) >> 3) & 0x70))

__device__ __forceinline__ uint32_t smem_u32(const void* p) {
    uint32_t a;
    asm("{ .reg .u64 t; cvta.to.shared.u64 t, %1; cvt.u32.u64 %0, t; }" : "=r"(a) : "l"(p));
    return a;
}

#define MMA_BF16(acc, A, B0, B1)                                               \
    asm volatile("mma.sync.aligned.m16n8k16.row.col.f32.bf16.bf16.f32 "        \
        "{%0,%1,%2,%3},{%4,%5,%6,%7},{%8,%9},{%0,%1,%2,%3};"                   \
        : "+f"((acc)[0]), "+f"((acc)[1]), "+f"((acc)[2]), "+f"((acc)[3])       \
        : "r"((A)[0]), "r"((A)[1]), "r"((A)[2]), "r"((A)[3]),                  \
          "r"(B0), "r"(B1))

#define CP_ASYNC16(dst_u32, src_ptr)                                           \
    asm volatile("cp.async.cg.shared.global [%0], [%1], 16;"                   \
                 :: "r"(dst_u32), "l"(src_ptr) : "memory")
#define CP_COMMIT() asm volatile("cp.async.commit_group;" ::: "memory")
#define CP_WAIT1()  asm volatile("cp.async.wait_group 1;" ::: "memory")
#define CP_WAIT0()  asm volatile("cp.async.wait_group 0;" ::: "memory")

// SMEM layout (dynamic)
#define SM_AH   0
#define SM_AL   16384
#define SM_B    32768            // two 32KB buffers (hi @ +0, lo @ +16384 within each)
#define SM_HN   (SM_B + 65536)   // 98304, 4KB floats
#define SM_IDX  (SM_HN + 4096)   // 102400, 2*128 ints
#define SM_TOTAL (SM_IDX + 1024 + 128)

// ---------------------------------------------------------------------------
// Prep: zero scratch, half-norms, bf16 hi/lo split of embedding
// ---------------------------------------------------------------------------
__global__ void vq_prep(const float* __restrict__ emb) {
    int i = blockIdx.x * 256 + threadIdx.x;   // 65536 threads
    g_dw[i] = 0.0f;
    if (i < KC) {
        g_counts[i] = 0.0f;
        const float* r = emb + (size_t)i * DD;
        float s = 0.0f;
        #pragma unroll
        for (int j = 0; j < DD; ++j) {
            float f = r[j];
            s += f * f;
            __nv_bfloat16 h = __float2bfloat16_rn(f);
            float lf = f - __bfloat162float(h);
            __nv_bfloat16 l = __float2bfloat16_rn(lf);
            g_ehi[i * DD + j] = reinterpret_cast<uint16_t&>(h);
            g_elo[i * DD + j] = reinterpret_cast<uint16_t&>(l);
        }
        g_hn[i] = 0.5f * s;
    }
    if (i == 0) g_loss = 0.0f;
}

// ---------------------------------------------------------------------------
// Main: HMMA bf16x3 distance GEMM + top-2 + exact rescore + epilogue
// ---------------------------------------------------------------------------
extern __shared__ __align__(1024) char smc[];

__device__ __forceinline__ void top2_merge(float& v1, int& i1, float& v2, int& i2,
                                           float w, int j) {
    if (w < v1)      { v2 = v1; i2 = i1; v1 = w; i1 = j; }
    else if (w < v2) { v2 = w; i2 = j; }
}

__device__ __forceinline__ void load_bchunk_async(uint32_t sb, int c, int buf, int tid) {
    #pragma unroll
    for (int i = 0; i < 16; ++i) {
        int idx  = tid + i * 128;            // 0..2047
        int part = idx >> 10;                // 0 = hi, 1 = lo
        int o    = idx & 1023;
        int code = o >> 3;
        int ch   = o & 7;
        const uint16_t* src = (part ? g_elo : g_ehi)
                            + (size_t)(c * 128 + code) * DD + ch * 8;
        uint32_t doff = SM_B + buf * 32768 + part * 16384
                      + code * 128 + ((ch ^ (code & 7)) * 16);
        CP_ASYNC16(sb + doff, src);
    }
}

__global__ __launch_bounds__(128) void vq_main_mma(
        const float* __restrict__ z,
        const float* __restrict__ emb,
        float* __restrict__ out) {
    __shared__ float swr[4];
    const int tid  = threadIdx.x;
    const int wid  = tid >> 5;
    const int lane = tid & 31;
    const uint32_t sb = smem_u32(smc);

    const int n = blockIdx.x * 128 + tid;
    const int b = n >> 11;
    const int t = n & 2047;
    const float* zp = z + (size_t)b * (DD * TT) + t;

    // --- Stage A: load z vector (coalesced), bf16 hi/lo split, swizzled store
    #pragma unroll
    for (int d = 0; d < DD; d += 2) {
        float f0 = zp[(size_t)d * TT];
        float f1 = zp[(size_t)(d + 1) * TT];
        __nv_bfloat16 h0 = __float2bfloat16_rn(f0);
        __nv_bfloat16 h1 = __float2bfloat16_rn(f1);
        __nv_bfloat16 l0 = __float2bfloat16_rn(f0 - __bfloat162float(h0));
        __nv_bfloat16 l1 = __float2bfloat16_rn(f1 - __bfloat162float(h1));
        uint32_t hp = (uint32_t)reinterpret_cast<uint16_t&>(h0)
                    | ((uint32_t)reinterpret_cast<uint16_t&>(h1) << 16);
        uint32_t lp = (uint32_t)reinterpret_cast<uint16_t&>(l0)
                    | ((uint32_t)reinterpret_cast<uint16_t&>(l1) << 16);
        uint32_t off = SWZ((uint32_t)(tid * 128 + 2 * d));
        *(uint32_t*)(smc + SM_AH + off) = hp;
        *(uint32_t*)(smc + SM_AL + off) = lp;
    }
    float* shn = (float*)(smc + SM_HN);
    #pragma unroll
    for (int i = 0; i < 8; ++i) shn[tid + i * 128] = g_hn[tid + i * 128];

    // Prefetch B chunks 0, 1
    load_bchunk_async(sb, 0, 0, tid); CP_COMMIT();
    load_bchunk_async(sb, 1, 1, tid); CP_COMMIT();

    __syncthreads();

    // --- Load A fragments into registers: 2 m-tiles x 4 k-steps x 4 regs, hi+lo
    uint32_t ah[2][4][4], al[2][4][4];
    #pragma unroll
    for (int mt = 0; mt < 2; ++mt) {
        int base_r = wid * 32 + mt * 16;
        #pragma unroll
        for (int s = 0; s < 4; ++s) {
            #pragma unroll
            for (int q = 0; q < 4; ++q) {
                int row = base_r + (lane >> 2) + (q & 1) * 8;
                uint32_t off = SWZ((uint32_t)(row * 128 + s * 32
                                  + (lane & 3) * 4 + (q >> 1) * 16));
                ah[mt][s][q] = *(const uint32_t*)(smc + SM_AH + off);
                al[mt][s][q] = *(const uint32_t*)(smc + SM_AL + off);
            }
        }
    }

    float tv1[4], tv2[4]; int ti1[4], ti2[4];
    #pragma unroll
    for (int s = 0; s < 4; ++s) { tv1[s] = 3.4e38f; tv2[s] = 3.4e38f; ti1[s] = 0; ti2[s] = 0; }

    // --- Chunk loop: 8 chunks x 128 codes
    for (int c = 0; c < 8; ++c) {
        if (c < 7) CP_WAIT1(); else CP_WAIT0();
        __syncthreads();
        const char* bb = smc + SM_B + (c & 1) * 32768;

        #pragma unroll 1
        for (int nt = 0; nt < 16; ++nt) {
            // B fragments: code row (tile-local) = nt*8 + lane/4
            int brow = nt * 8 + (lane >> 2);
            uint32_t bh[4][2], bl[4][2];
            #pragma unroll
            for (int s = 0; s < 4; ++s) {
                uint32_t o0 = SWZ((uint32_t)(brow * 128 + s * 32 + (lane & 3) * 4));
                uint32_t o1 = SWZ((uint32_t)(brow * 128 + s * 32 + (lane & 3) * 4 + 16));
                bh[s][0] = *(const uint32_t*)(bb + o0);
                bh[s][1] = *(const uint32_t*)(bb + o1);
                bl[s][0] = *(const uint32_t*)(bb + 16384 + o0);
                bl[s][1] = *(const uint32_t*)(bb + 16384 + o1);
            }
            float acc0[4] = {0.f, 0.f, 0.f, 0.f};
            float acc1[4] = {0.f, 0.f, 0.f, 0.f};
            #pragma unroll
            for (int s = 0; s < 4; ++s) {
                MMA_BF16(acc0, ah[0][s], bh[s][0], bh[s][1]);
                MMA_BF16(acc0, ah[0][s], bl[s][0], bl[s][1]);
                MMA_BF16(acc0, al[0][s], bh[s][0], bh[s][1]);
                MMA_BF16(acc1, ah[1][s], bh[s][0], bh[s][1]);
                MMA_BF16(acc1, ah[1][s], bl[s][0], bl[s][1]);
                MMA_BF16(acc1, al[1][s], bh[s][0], bh[s][1]);
            }
            int c0 = c * 128 + nt * 8 + (lane & 3) * 2;
            float h0 = shn[c0], h1 = shn[c0 + 1];
            top2_merge(tv1[0], ti1[0], tv2[0], ti2[0], h0 - acc0[0], c0);
            top2_merge(tv1[0], ti1[0], tv2[0], ti2[0], h1 - acc0[1], c0 + 1);
            top2_merge(tv1[1], ti1[1], tv2[1], ti2[1], h0 - acc0[2], c0);
            top2_merge(tv1[1], ti1[1], tv2[1], ti2[1], h1 - acc0[3], c0 + 1);
            top2_merge(tv1[2], ti1[2], tv2[2], ti2[2], h0 - acc1[0], c0);
            top2_merge(tv1[2], ti1[2], tv2[2], ti2[2], h1 - acc1[1], c0 + 1);
            top2_merge(tv1[3], ti1[3], tv2[3], ti2[3], h0 - acc1[2], c0);
            top2_merge(tv1[3], ti1[3], tv2[3], ti2[3], h1 - acc1[3], c0 + 1);
        }
        __syncthreads();
        if (c < 6) { load_bchunk_async(sb, c + 2, c & 1, tid); CP_COMMIT(); }
    }

    // --- Cross-lane top-2 reduce over the 4 lanes sharing each row
    int* si = (int*)(smc + SM_IDX);
    #pragma unroll
    for (int s = 0; s < 4; ++s) {
        #pragma unroll
        for (int off = 1; off <= 2; off <<= 1) {
            float w1 = __shfl_xor_sync(0xffffffffu, tv1[s], off);
            float w2 = __shfl_xor_sync(0xffffffffu, tv2[s], off);
            int   j1 = __shfl_xor_sync(0xffffffffu, ti1[s], off);
            int   j2 = __shfl_xor_sync(0xffffffffu, ti2[s], off);
            top2_merge(tv1[s], ti1[s], tv2[s], ti2[s], w1, j1);
            top2_merge(tv1[s], ti1[s], tv2[s], ti2[s], w2, j2);
        }
        if ((lane & 3) == 0) {
            int mt = s >> 1, half = s & 1;
            int r = wid * 32 + mt * 16 + half * 8 + (lane >> 2);
            si[r]       = ti1[s];
            si[128 + r] = ti2[s];
        }
    }
    __syncthreads();

    // --- Exact fp32 rescore of the two candidates for this thread's vector
    int i1 = si[tid], i2 = si[128 + tid];
    float d1 = 0.0f, d2 = 0.0f;
    {
        const float* e1 = emb + (size_t)i1 * DD;
        const float* e2 = emb + (size_t)i2 * DD;
        #pragma unroll
        for (int d = 0; d < DD; ++d) {
            float xv = zp[(size_t)d * TT];
            d1 = fmaf(xv, e1[d], d1);
            d2 = fmaf(xv, e2[d], d2);
        }
    }
    float ve1 = g_hn[i1] - d1;
    float ve2 = g_hn[i2] - d2;
    int besti = (ve2 < ve1 || (ve2 == ve1 && i2 < i1)) ? i2 : i1;

    // --- Epilogue: quantized write, loss, codes, segment sums
    const float4* er = (const float4*)(emb + (size_t)besti * DD);
    float* oq = out + OFF_Q + (size_t)b * (DD * TT) + t;
    float* dwp = g_dw + (size_t)besti * DD;
    float lsum = 0.0f;
    #pragma unroll
    for (int j = 0; j < 16; ++j) {
        float4 e4 = __ldg(er + j);
        float x0 = zp[(size_t)(4 * j + 0) * TT];
        float x1 = zp[(size_t)(4 * j + 1) * TT];
        float x2 = zp[(size_t)(4 * j + 2) * TT];
        float x3 = zp[(size_t)(4 * j + 3) * TT];
        oq[(size_t)(4 * j + 0) * TT] = e4.x;
        oq[(size_t)(4 * j + 1) * TT] = e4.y;
        oq[(size_t)(4 * j + 2) * TT] = e4.z;
        oq[(size_t)(4 * j + 3) * TT] = e4.w;
        float q0 = e4.x - x0, q1 = e4.y - x1, q2 = e4.z - x2, q3 = e4.w - x3;
        lsum += q0 * q0 + q1 * q1 + q2 * q2 + q3 * q3;
        asm volatile("red.global.add.v4.f32 [%0], {%1,%2,%3,%4};"
                     :: "l"(dwp + 4 * j), "f"(x0), "f"(x1), "f"(x2), "f"(x3) : "memory");
    }
    out[OFF_CODES + n] = (float)besti;
    atomicAdd(&g_counts[besti], 1.0f);

    #pragma unroll
    for (int o = 16; o; o >>= 1) lsum += __shfl_xor_sync(0xffffffffu, lsum, o);
    if (lane == 0) swr[wid] = lsum;
    __syncthreads();
    if (tid == 0)
        atomicAdd(&g_loss, swr[0] + swr[1] + swr[2] + swr[3]);
}

// ---------------------------------------------------------------------------
// Finalize 1: new_cs, cluster-size normalization, loss
// ---------------------------------------------------------------------------
__global__ __launch_bounds__(1024) void vq_fin1(
        const float* __restrict__ ema_cs, float* __restrict__ out) {
    __shared__ float sw[32];
    __shared__ float snv;
    int k = threadIdx.x;
    float cs = DECAYF * ema_cs[k] + OMD * g_counts[k];
    out[OFF_NEWCS + k] = cs;

    float v = cs;
    #pragma unroll
    for (int o = 16; o; o >>= 1) v += __shfl_xor_sync(0xffffffffu, v, o);
    if ((k & 31) == 0) sw[k >> 5] = v;
    __syncthreads();
    if (k < 32) {
        float u = sw[k];
        #pragma unroll
        for (int o = 16; o; o >>= 1) u += __shfl_xor_sync(0xffffffffu, u, o);
        if (k == 0) snv = u;
    }
    __syncthreads();
    float nsum = snv;
    float cluster = (cs + EPSF) / (nsum + (float)KC * EPSF) * nsum;
    g_invcs[k] = 1.0f / cluster;
    if (k == 0) out[OFF_LOSS] = COMMITF * g_loss * (1.0f / (float)QE);
}

// ---------------------------------------------------------------------------
// Finalize 2: new_w, new_embedding
// ---------------------------------------------------------------------------
__global__ __launch_bounds__(256) void vq_fin2(
        const float* __restrict__ ema_w, float* __restrict__ out) {
    int i = blockIdx.x * 256 + threadIdx.x;
    float nw = DECAYF * ema_w[i] + OMD * g_dw[i];
    out[OFF_NEWW + i] = nw;
    out[OFF_NEWEMB + i] = nw * g_invcs[i >> 6];
}

// ---------------------------------------------------------------------------
extern "C" void kernel_launch(void* const* d_in, const int* in_sizes, int n_in,
                              void* d_out, int out_size) {
    const float* z      = (const float*)d_in[0];
    const float* emb    = (const float*)d_in[1];
    const float* ema_cs = (const float*)d_in[2];
    const float* ema_w  = (const float*)d_in[3];
    float* out = (float*)d_out;

    cudaFuncSetAttribute(vq_main_mma, cudaFuncAttributeMaxDynamicSharedMemorySize, SM_TOTAL);

    vq_prep<<<256, 256>>>(emb);
    vq_main_mma<<<512, 128, SM_TOTAL>>>(z, emb, out);
    vq_fin1<<<1, 1024>>>(ema_cs, out);
    vq_fin2<<<256, 256>>>(ema_w, out);
}

// round 6
// speedup vs baseline: 1.8133x; 1.8133x over previous
#include <cuda_runtime.h>
#include <cuda_bf16.h>
#include <cstdint>

// Problem constants
#define KC   1024
#define DD   64
#define BB   32
#define TT   2048
#define NV   (BB*TT)
#define QE   (BB*DD*TT)
#define DECAYF 0.99f
#define OMD    (1.0f - 0.99f)
#define COMMITF 0.25f
#define EPSF 1e-5f
#define NCAND 6

// Output layout (flat float32, reference tuple order)
#define OFF_Q      0
#define OFF_LOSS   (OFF_Q + QE)
#define OFF_CODES  (OFF_LOSS + 1)
#define OFF_NEWEMB (OFF_CODES + NV)
#define OFF_NEWCS  (OFF_NEWEMB + KC*DD)
#define OFF_NEWW   (OFF_NEWCS + KC)

// Scratch (device globals — no allocation)
__device__ float g_hn[KC];
__device__ float g_counts[KC];
__device__ float g_dw[KC*DD];
__device__ float g_invcs[KC];
__device__ float g_loss;
__device__ __align__(256) uint16_t g_ehi[KC*DD];   // bf16 hi part of embedding

#define SWZ(o) ((o) ^ (((o) >> 3) & 0x70))

__device__ __forceinline__ uint32_t smem_u32(const void* p) {
    uint32_t a;
    asm("{ .reg .u64 t; cvta.to.shared.u64 t, %1; cvt.u32.u64 %0, t; }" : "=r"(a) : "l"(p));
    return a;
}

#define MMA_BF16(acc, A, B0, B1)                                               \
    asm volatile("mma.sync.aligned.m16n8k16.row.col.f32.bf16.bf16.f32 "        \
        "{%0,%1,%2,%3},{%4,%5,%6,%7},{%8,%9},{%0,%1,%2,%3};"                   \
        : "+f"((acc)[0]), "+f"((acc)[1]), "+f"((acc)[2]), "+f"((acc)[3])       \
        : "r"((A)[0]), "r"((A)[1]), "r"((A)[2]), "r"((A)[3]),                  \
          "r"(B0), "r"(B1))

#define CP_ASYNC16(dst_u32, src_ptr)                                           \
    asm volatile("cp.async.cg.shared.global [%0], [%1], 16;"                   \
                 :: "r"(dst_u32), "l"(src_ptr) : "memory")
#define CP_COMMIT() asm volatile("cp.async.commit_group;" ::: "memory")
#define CP_WAIT1()  asm volatile("cp.async.wait_group 1;" ::: "memory")
#define CP_WAIT0()  asm volatile("cp.async.wait_group 0;" ::: "memory")

// SMEM layout (dynamic): A-hi 16KB | B double buffer 2x16KB | hn 4KB
#define SM_AH    0
#define SM_B     16384
#define SM_HN    49152
#define SM_CAND  SM_AH                  // reused after MMA loop (128*6 ints)
#define SM_TOTAL (SM_HN + 4096 + 128)

// ---------------------------------------------------------------------------
// Prep: zero scratch, half-norms, bf16 hi split of embedding
// ---------------------------------------------------------------------------
__global__ void vq_prep(const float* __restrict__ emb) {
    int i = blockIdx.x * 256 + threadIdx.x;   // 65536 threads
    g_dw[i] = 0.0f;
    {
        __nv_bfloat16 h = __float2bfloat16_rn(emb[i]);
        g_ehi[i] = reinterpret_cast<uint16_t&>(h);
    }
    if (i < KC) {
        g_counts[i] = 0.0f;
        const float4* r = (const float4*)(emb + (size_t)i * DD);
        float s = 0.0f;
        #pragma unroll
        for (int j = 0; j < 16; ++j) {
            float4 v = r[j];
            s += v.x * v.x + v.y * v.y + v.z * v.z + v.w * v.w;
        }
        g_hn[i] = 0.5f * s;
    }
    if (i == 0) g_loss = 0.0f;
}

// ---------------------------------------------------------------------------
// Main: 1-term HMMA screen + per-lane top-4 + merged top-6 exact rescore
// ---------------------------------------------------------------------------
extern __shared__ __align__(1024) char smc[];

// Branchless sorted insert (ascending, keep 4 smallest). Packed floats.
__device__ __forceinline__ void ins4(float v[4], float w) {
    float t = w;
    #pragma unroll
    for (int i = 0; i < 4; ++i) {
        float lo = fminf(t, v[i]);
        t = fmaxf(t, v[i]);
        v[i] = lo;
    }
}
__device__ __forceinline__ void ins6(float v[6], float w) {
    float t = w;
    #pragma unroll
    for (int i = 0; i < 6; ++i) {
        float lo = fminf(t, v[i]);
        t = fmaxf(t, v[i]);
        v[i] = lo;
    }
}
__device__ __forceinline__ float packsi(float s, int idx) {
    return __uint_as_float((__float_as_uint(s) & 0xFFFFFC00u) | (uint32_t)idx);
}

__device__ __forceinline__ void load_bchunk_async(uint32_t sb, int c, int buf, int tid) {
    #pragma unroll
    for (int i = 0; i < 8; ++i) {
        int idx  = tid + i * 128;            // 0..1023
        int code = idx >> 3;
        int ch   = idx & 7;
        const uint16_t* src = g_ehi + (size_t)(c * 128 + code) * DD + ch * 8;
        uint32_t doff = SM_B + buf * 16384 + code * 128 + ((ch ^ (code & 7)) * 16);
        CP_ASYNC16(sb + doff, src);
    }
}

__global__ __launch_bounds__(128, 4) void vq_main_mma(
        const float* __restrict__ z,
        const float* __restrict__ emb,
        float* __restrict__ out) {
    __shared__ float swr[4];
    const int tid  = threadIdx.x;
    const int wid  = tid >> 5;
    const int lane = tid & 31;
    const uint32_t sb = smem_u32(smc);

    const int n = blockIdx.x * 128 + tid;
    const int b = n >> 11;
    const int t = n & 2047;
    const float* zp = z + (size_t)b * (DD * TT) + t;

    // --- Stage A: load z vector (coalesced), bf16 hi, swizzled store
    #pragma unroll
    for (int d = 0; d < DD; d += 2) {
        float f0 = zp[(size_t)d * TT];
        float f1 = zp[(size_t)(d + 1) * TT];
        __nv_bfloat16 h0 = __float2bfloat16_rn(f0);
        __nv_bfloat16 h1 = __float2bfloat16_rn(f1);
        uint32_t hp = (uint32_t)reinterpret_cast<uint16_t&>(h0)
                    | ((uint32_t)reinterpret_cast<uint16_t&>(h1) << 16);
        uint32_t off = SWZ((uint32_t)(tid * 128 + 2 * d));
        *(uint32_t*)(smc + SM_AH + off) = hp;
    }
    float* shn = (float*)(smc + SM_HN);
    #pragma unroll
    for (int i = 0; i < 8; ++i) shn[tid + i * 128] = g_hn[tid + i * 128];

    // Prefetch B chunks 0, 1
    load_bchunk_async(sb, 0, 0, tid); CP_COMMIT();
    load_bchunk_async(sb, 1, 1, tid); CP_COMMIT();

    __syncthreads();

    // --- A fragments: 2 m-tiles x 4 k-steps x 4 regs
    uint32_t ah[2][4][4];
    #pragma unroll
    for (int mt = 0; mt < 2; ++mt) {
        int base_r = wid * 32 + mt * 16;
        #pragma unroll
        for (int s = 0; s < 4; ++s) {
            #pragma unroll
            for (int q = 0; q < 4; ++q) {
                int row = base_r + (lane >> 2) + (q & 1) * 8;
                uint32_t off = SWZ((uint32_t)(row * 128 + s * 32
                                  + (lane & 3) * 4 + (q >> 1) * 16));
                ah[mt][s][q] = *(const uint32_t*)(smc + SM_AH + off);
            }
        }
    }

    // Per-slot top-4 trackers (packed score|index floats)
    float tv[4][4];
    #pragma unroll
    for (int s = 0; s < 4; ++s)
        #pragma unroll
        for (int j = 0; j < 4; ++j) tv[s][j] = 1.0e38f;

    // --- Chunk loop: 8 chunks x 128 codes
    for (int c = 0; c < 8; ++c) {
        if (c < 7) CP_WAIT1(); else CP_WAIT0();
        __syncthreads();
        const char* bb = smc + SM_B + (c & 1) * 16384;

        #pragma unroll 1
        for (int nt = 0; nt < 16; ++nt) {
            int brow = nt * 8 + (lane >> 2);
            uint32_t bh[4][2];
            #pragma unroll
            for (int s = 0; s < 4; ++s) {
                uint32_t o0 = SWZ((uint32_t)(brow * 128 + s * 32 + (lane & 3) * 4));
                uint32_t o1 = SWZ((uint32_t)(brow * 128 + s * 32 + (lane & 3) * 4 + 16));
                bh[s][0] = *(const uint32_t*)(bb + o0);
                bh[s][1] = *(const uint32_t*)(bb + o1);
            }
            float acc0[4] = {0.f, 0.f, 0.f, 0.f};
            float acc1[4] = {0.f, 0.f, 0.f, 0.f};
            #pragma unroll
            for (int s = 0; s < 4; ++s) {
                MMA_BF16(acc0, ah[0][s], bh[s][0], bh[s][1]);
                MMA_BF16(acc1, ah[1][s], bh[s][0], bh[s][1]);
            }
            int c0 = c * 128 + nt * 8 + (lane & 3) * 2;
            float h0 = shn[c0], h1 = shn[c0 + 1];
            ins4(tv[0], packsi(h0 - acc0[0], c0));
            ins4(tv[0], packsi(h1 - acc0[1], c0 + 1));
            ins4(tv[1], packsi(h0 - acc0[2], c0));
            ins4(tv[1], packsi(h1 - acc0[3], c0 + 1));
            ins4(tv[2], packsi(h0 - acc1[0], c0));
            ins4(tv[2], packsi(h1 - acc1[1], c0 + 1));
            ins4(tv[3], packsi(h0 - acc1[2], c0));
            ins4(tv[3], packsi(h1 - acc1[3], c0 + 1));
        }
        __syncthreads();
        if (c < 6) { load_bchunk_async(sb, c + 2, c & 1, tid); CP_COMMIT(); }
    }

    // --- Cross-lane butterfly merge (4 lanes, disjoint code sets) -> top-6
    int* ci = (int*)(smc + SM_CAND);
    #pragma unroll
    for (int s = 0; s < 4; ++s) {
        float m[6] = {tv[s][0], tv[s][1], tv[s][2], tv[s][3], 1.0e38f, 1.0e38f};
        #pragma unroll
        for (int off = 1; off <= 2; off <<= 1) {
            float p[6];
            #pragma unroll
            for (int j = 0; j < 6; ++j) p[j] = __shfl_xor_sync(0xffffffffu, m[j], off);
            #pragma unroll
            for (int j = 0; j < 6; ++j) ins6(m, p[j]);
        }
        if ((lane & 3) == 0) {
            int row = wid * 32 + (s >> 1) * 16 + (s & 1) * 8 + (lane >> 2);
            #pragma unroll
            for (int j = 0; j < NCAND; ++j)
                ci[row * NCAND + j] = (int)(__float_as_uint(m[j]) & 1023u);
        }
    }
    __syncthreads();

    // --- Load x into registers (coalesced), exact fp32 rescore of 6 cands
    float xr[DD];
    #pragma unroll
    for (int d = 0; d < DD; ++d) xr[d] = zp[(size_t)d * TT];

    float bestv = 3.4e38f;
    int   besti = 0;
    #pragma unroll
    for (int j = 0; j < NCAND; ++j) {
        int idx = ci[tid * NCAND + j];
        const float4* er = (const float4*)(emb + (size_t)idx * DD);
        float dot = 0.0f;
        #pragma unroll
        for (int q = 0; q < 16; ++q) {
            float4 e4 = __ldg(er + q);
            dot = fmaf(xr[4 * q + 0], e4.x, dot);
            dot = fmaf(xr[4 * q + 1], e4.y, dot);
            dot = fmaf(xr[4 * q + 2], e4.z, dot);
            dot = fmaf(xr[4 * q + 3], e4.w, dot);
        }
        float v = g_hn[idx] - dot;
        if (v < bestv || (v == bestv && idx < besti)) { bestv = v; besti = idx; }
    }

    // --- Epilogue: quantized write, loss, codes, segment sums
    const float4* er = (const float4*)(emb + (size_t)besti * DD);
    float* oq = out + OFF_Q + (size_t)b * (DD * TT) + t;
    float* dwp = g_dw + (size_t)besti * DD;
    float lsum = 0.0f;
    #pragma unroll
    for (int j = 0; j < 16; ++j) {
        float4 e4 = __ldg(er + j);
        float x0 = xr[4 * j + 0], x1 = xr[4 * j + 1];
        float x2 = xr[4 * j + 2], x3 = xr[4 * j + 3];
        oq[(size_t)(4 * j + 0) * TT] = e4.x;
        oq[(size_t)(4 * j + 1) * TT] = e4.y;
        oq[(size_t)(4 * j + 2) * TT] = e4.z;
        oq[(size_t)(4 * j + 3) * TT] = e4.w;
        float q0 = e4.x - x0, q1 = e4.y - x1, q2 = e4.z - x2, q3 = e4.w - x3;
        lsum += q0 * q0 + q1 * q1 + q2 * q2 + q3 * q3;
        asm volatile("red.global.add.v4.f32 [%0], {%1,%2,%3,%4};"
                     :: "l"(dwp + 4 * j), "f"(x0), "f"(x1), "f"(x2), "f"(x3) : "memory");
    }
    out[OFF_CODES + n] = (float)besti;
    atomicAdd(&g_counts[besti], 1.0f);

    #pragma unroll
    for (int o = 16; o; o >>= 1) lsum += __shfl_xor_sync(0xffffffffu, lsum, o);
    if (lane == 0) swr[wid] = lsum;
    __syncthreads();
    if (tid == 0)
        atomicAdd(&g_loss, swr[0] + swr[1] + swr[2] + swr[3]);
}

// ---------------------------------------------------------------------------
// Finalize 1: new_cs, cluster-size normalization, loss
// ---------------------------------------------------------------------------
__global__ __launch_bounds__(1024) void vq_fin1(
        const float* __restrict__ ema_cs, float* __restrict__ out) {
    __shared__ float sw[32];
    __shared__ float snv;
    int k = threadIdx.x;
    float cs = DECAYF * ema_cs[k] + OMD * g_counts[k];
    out[OFF_NEWCS + k] = cs;

    float v = cs;
    #pragma unroll
    for (int o = 16; o; o >>= 1) v += __shfl_xor_sync(0xffffffffu, v, o);
    if ((k & 31) == 0) sw[k >> 5] = v;
    __syncthreads();
    if (k < 32) {
        float u = sw[k];
        #pragma unroll
        for (int o = 16; o; o >>= 1) u += __shfl_xor_sync(0xffffffffu, u, o);
        if (k == 0) snv = u;
    }
    __syncthreads();
    float nsum = snv;
    float cluster = (cs + EPSF) / (nsum + (float)KC * EPSF) * nsum;
    g_invcs[k] = 1.0f / cluster;
    if (k == 0) out[OFF_LOSS] = COMMITF * g_loss * (1.0f / (float)QE);
}

// ---------------------------------------------------------------------------
// Finalize 2: new_w, new_embedding
// ---------------------------------------------------------------------------
__global__ __launch_bounds__(256) void vq_fin2(
        const float* __restrict__ ema_w, float* __restrict__ out) {
    int i = blockIdx.x * 256 + threadIdx.x;
    float nw = DECAYF * ema_w[i] + OMD * g_dw[i];
    out[OFF_NEWW + i] = nw;
    out[OFF_NEWEMB + i] = nw * g_invcs[i >> 6];
}

// ---------------------------------------------------------------------------
extern "C" void kernel_launch(void* const* d_in, const int* in_sizes, int n_in,
                              void* d_out, int out_size) {
    const float* z      = (const float*)d_in[0];
    const float* emb    = (const float*)d_in[1];
    const float* ema_cs = (const float*)d_in[2];
    const float* ema_w  = (const float*)d_in[3];
    float* out = (float*)d_out;

    cudaFuncSetAttribute(vq_main_mma, cudaFuncAttributeMaxDynamicSharedMemorySize, SM_TOTAL);

    vq_prep<<<256, 256>>>(emb);
    vq_main_mma<<<512, 128, SM_TOTAL>>>(z, emb, out);
    vq_fin1<<<1, 1024>>>(ema_cs, out);
    vq_fin2<<<256, 256>>>(ema_w, out);
}

// round 7
// speedup vs baseline: 1.9724x; 1.0877x over previous
#include <cuda_runtime.h>
#include <cuda_bf16.h>
#include <cstdint>

// Problem constants
#define KC   1024
#define DD   64
#define BB   32
#define TT   2048
#define NV   (BB*TT)
#define QE   (BB*DD*TT)
#define DECAYF 0.99f
#define OMD    (1.0f - 0.99f)
#define COMMITF 0.25f
#define EPSF 1e-5f
#define NCAND 6

// Output layout (flat float32, reference tuple order)
#define OFF_Q      0
#define OFF_LOSS   (OFF_Q + QE)
#define OFF_CODES  (OFF_LOSS + 1)
#define OFF_NEWEMB (OFF_CODES + NV)
#define OFF_NEWCS  (OFF_NEWEMB + KC*DD)
#define OFF_NEWW   (OFF_NEWCS + KC)

// Scratch (device globals — no allocation)
__device__ float g_hn[KC];
__device__ float g_counts[KC];
__device__ float g_dw[KC*DD];
__device__ float g_invcs[KC];
__device__ float g_loss;
__device__ __align__(256) uint16_t g_ehi[KC*DD];   // bf16 hi part of embedding

#define SWZ(o) ((o) ^ (((o) >> 3) & 0x70))

__device__ __forceinline__ uint32_t smem_u32(const void* p) {
    uint32_t a;
    asm("{ .reg .u64 t; cvta.to.shared.u64 t, %1; cvt.u32.u64 %0, t; }" : "=r"(a) : "l"(p));
    return a;
}

#define MMA_BF16(acc, A, B0, B1)                                               \
    asm volatile("mma.sync.aligned.m16n8k16.row.col.f32.bf16.bf16.f32 "        \
        "{%0,%1,%2,%3},{%4,%5,%6,%7},{%8,%9},{%0,%1,%2,%3};"                   \
        : "+f"((acc)[0]), "+f"((acc)[1]), "+f"((acc)[2]), "+f"((acc)[3])       \
        : "r"((A)[0]), "r"((A)[1]), "r"((A)[2]), "r"((A)[3]),                  \
          "r"(B0), "r"(B1))

#define CP_ASYNC16(dst_u32, src_ptr)                                           \
    asm volatile("cp.async.cg.shared.global [%0], [%1], 16;"                   \
                 :: "r"(dst_u32), "l"(src_ptr) : "memory")
#define CP_COMMIT() asm volatile("cp.async.commit_group;" ::: "memory")
#define CP_WAIT1()  asm volatile("cp.async.wait_group 1;" ::: "memory")
#define CP_WAIT0()  asm volatile("cp.async.wait_group 0;" ::: "memory")

// SMEM layout (dynamic): A-hi 16KB | B double buffer 2x16KB | hn 4KB
#define SM_AH    0
#define SM_B     16384
#define SM_HN    49152
#define SM_CAND  SM_AH                  // reused after MMA loop (128*6 ints)
#define SM_TOTAL (SM_HN + 4096 + 128)

// ---------------------------------------------------------------------------
// Prep: zero scratch, half-norms, bf16 hi split of embedding
// ---------------------------------------------------------------------------
__global__ void vq_prep(const float* __restrict__ emb) {
    int i = blockIdx.x * 256 + threadIdx.x;   // 65536 threads
    g_dw[i] = 0.0f;
    {
        __nv_bfloat16 h = __float2bfloat16_rn(emb[i]);
        g_ehi[i] = reinterpret_cast<uint16_t&>(h);
    }
    if (i < KC) {
        g_counts[i] = 0.0f;
        const float4* r = (const float4*)(emb + (size_t)i * DD);
        float s = 0.0f;
        #pragma unroll
        for (int j = 0; j < 16; ++j) {
            float4 v = r[j];
            s += v.x * v.x + v.y * v.y + v.z * v.z + v.w * v.w;
        }
        g_hn[i] = 0.5f * s;
    }
    if (i == 0) g_loss = 0.0f;
}

// ---------------------------------------------------------------------------
// Main: 1-term HMMA screen (score in accumulator) + lane top-3 + top-6 rescore
// ---------------------------------------------------------------------------
extern __shared__ __align__(1024) char smc[];

// Merge 2 new values into sorted ascending top-3 (v0<=v1<=v2). 9 FMNMX.
__device__ __forceinline__ void insp3(float v[3], float a, float b) {
    float a0 = fminf(a, b), a1 = fmaxf(a, b);
    float x0 = fminf(v[0], a0), y0 = fmaxf(v[0], a0);
    float x1 = fminf(v[1], a1), y1 = fmaxf(v[1], a1);
    v[0] = x0;
    v[1] = fminf(y0, x1);
    v[2] = fminf(fmaxf(y0, x1), fminf(v[2], y1));
}
__device__ __forceinline__ void ins6(float v[6], float w) {
    float t = w;
    #pragma unroll
    for (int i = 0; i < 6; ++i) {
        float lo = fminf(t, v[i]);
        t = fmaxf(t, v[i]);
        v[i] = lo;
    }
}
// Single LOP3: clear 10 low mantissa bits, insert index
__device__ __forceinline__ float packsi(float s, uint32_t idx) {
    return __uint_as_float((__float_as_uint(s) & 0xFFFFFC00u) | idx);
}

__device__ __forceinline__ void load_bchunk_async(uint32_t sb, int c, int buf, int tid) {
    #pragma unroll
    for (int i = 0; i < 8; ++i) {
        int idx  = tid + i * 128;            // 0..1023
        int code = idx >> 3;
        int ch   = idx & 7;
        const uint16_t* src = g_ehi + (size_t)(c * 128 + code) * DD + ch * 8;
        uint32_t doff = SM_B + buf * 16384 + code * 128 + ((ch ^ (code & 7)) * 16);
        CP_ASYNC16(sb + doff, src);
    }
}

__global__ __launch_bounds__(128, 4) void vq_main_mma(
        const float* __restrict__ z,
        const float* __restrict__ emb,
        float* __restrict__ out) {
    __shared__ float swr[4];
    const int tid  = threadIdx.x;
    const int wid  = tid >> 5;
    const int lane = tid & 31;
    const uint32_t sb = smem_u32(smc);

    const int n = blockIdx.x * 128 + tid;
    const int b = n >> 11;
    const int t = n & 2047;
    const float* zp = z + (size_t)b * (DD * TT) + t;

    // --- Stage A: load z (coalesced), NEGATED bf16 hi, swizzled store
    #pragma unroll
    for (int d = 0; d < DD; d += 2) {
        float f0 = -zp[(size_t)d * TT];
        float f1 = -zp[(size_t)(d + 1) * TT];
        __nv_bfloat16 h0 = __float2bfloat16_rn(f0);
        __nv_bfloat16 h1 = __float2bfloat16_rn(f1);
        uint32_t hp = (uint32_t)reinterpret_cast<uint16_t&>(h0)
                    | ((uint32_t)reinterpret_cast<uint16_t&>(h1) << 16);
        uint32_t off = SWZ((uint32_t)(tid * 128 + 2 * d));
        *(uint32_t*)(smc + SM_AH + off) = hp;
    }
    float* shn = (float*)(smc + SM_HN);
    #pragma unroll
    for (int i = 0; i < 8; ++i) shn[tid + i * 128] = g_hn[tid + i * 128];

    // Prefetch B chunks 0, 1
    load_bchunk_async(sb, 0, 0, tid); CP_COMMIT();
    load_bchunk_async(sb, 1, 1, tid); CP_COMMIT();

    __syncthreads();

    // --- A fragments: 2 m-tiles x 4 k-steps x 4 regs (hold -x)
    uint32_t ah[2][4][4];
    #pragma unroll
    for (int mt = 0; mt < 2; ++mt) {
        int base_r = wid * 32 + mt * 16;
        #pragma unroll
        for (int s = 0; s < 4; ++s) {
            #pragma unroll
            for (int q = 0; q < 4; ++q) {
                int row = base_r + (lane >> 2) + (q & 1) * 8;
                uint32_t off = SWZ((uint32_t)(row * 128 + s * 32
                                  + (lane & 3) * 4 + (q >> 1) * 16));
                ah[mt][s][q] = *(const uint32_t*)(smc + SM_AH + off);
            }
        }
    }

    // Per-slot sorted top-3 trackers (packed score|index floats)
    float tv[4][3];
    #pragma unroll
    for (int s = 0; s < 4; ++s)
        #pragma unroll
        for (int j = 0; j < 3; ++j) tv[s][j] = 1.0e38f;

    // --- Chunk loop: 8 chunks x 128 codes
    for (int c = 0; c < 8; ++c) {
        if (c < 7) CP_WAIT1(); else CP_WAIT0();
        __syncthreads();
        const char* bb = smc + SM_B + (c & 1) * 16384;

        #pragma unroll 1
        for (int nt = 0; nt < 16; ++nt) {
            int brow = nt * 8 + (lane >> 2);
            uint32_t bh[4][2];
            #pragma unroll
            for (int s = 0; s < 4; ++s) {
                uint32_t o0 = SWZ((uint32_t)(brow * 128 + s * 32 + (lane & 3) * 4));
                uint32_t o1 = SWZ((uint32_t)(brow * 128 + s * 32 + (lane & 3) * 4 + 16));
                bh[s][0] = *(const uint32_t*)(bb + o0);
                bh[s][1] = *(const uint32_t*)(bb + o1);
            }
            uint32_t c0 = (uint32_t)(c * 128 + nt * 8 + (lane & 3) * 2);
            float h0 = shn[c0], h1 = shn[c0 + 1];
            // acc initialized to h: score = h + (-x)·e lands directly in acc
            float acc0[4] = {h0, h1, h0, h1};
            float acc1[4] = {h0, h1, h0, h1};
            #pragma unroll
            for (int s = 0; s < 4; ++s) {
                MMA_BF16(acc0, ah[0][s], bh[s][0], bh[s][1]);
                MMA_BF16(acc1, ah[1][s], bh[s][0], bh[s][1]);
            }
            insp3(tv[0], packsi(acc0[0], c0), packsi(acc0[1], c0 + 1));
            insp3(tv[1], packsi(acc0[2], c0), packsi(acc0[3], c0 + 1));
            insp3(tv[2], packsi(acc1[0], c0), packsi(acc1[1], c0 + 1));
            insp3(tv[3], packsi(acc1[2], c0), packsi(acc1[3], c0 + 1));
        }
        __syncthreads();
        if (c < 6) { load_bchunk_async(sb, c + 2, c & 1, tid); CP_COMMIT(); }
    }

    // --- Cross-lane butterfly merge (4 lanes, disjoint code sets) -> top-6
    int* ci = (int*)(smc + SM_CAND);
    #pragma unroll
    for (int s = 0; s < 4; ++s) {
        float m[6] = {tv[s][0], tv[s][1], tv[s][2], 1.0e38f, 1.0e38f, 1.0e38f};
        #pragma unroll
        for (int off = 1; off <= 2; off <<= 1) {
            float p[6];
            #pragma unroll
            for (int j = 0; j < 6; ++j) p[j] = __shfl_xor_sync(0xffffffffu, m[j], off);
            #pragma unroll
            for (int j = 0; j < 6; ++j) ins6(m, p[j]);
        }
        if ((lane & 3) == 0) {
            int row = wid * 32 + (s >> 1) * 16 + (s & 1) * 8 + (lane >> 2);
            #pragma unroll
            for (int j = 0; j < NCAND; ++j)
                ci[row * NCAND + j] = (int)(__float_as_uint(m[j]) & 1023u);
        }
    }
    __syncthreads();

    // --- Load x into registers (coalesced), exact fp32 rescore of 6 cands
    float xr[DD];
    #pragma unroll
    for (int d = 0; d < DD; ++d) xr[d] = zp[(size_t)d * TT];

    float bestv = 3.4e38f;
    int   besti = 0;
    #pragma unroll
    for (int j = 0; j < NCAND; ++j) {
        int idx = ci[tid * NCAND + j];
        const float4* er = (const float4*)(emb + (size_t)idx * DD);
        float dot = 0.0f;
        #pragma unroll
        for (int q = 0; q < 16; ++q) {
            float4 e4 = __ldg(er + q);
            dot = fmaf(xr[4 * q + 0], e4.x, dot);
            dot = fmaf(xr[4 * q + 1], e4.y, dot);
            dot = fmaf(xr[4 * q + 2], e4.z, dot);
            dot = fmaf(xr[4 * q + 3], e4.w, dot);
        }
        float v = g_hn[idx] - dot;
        if (v < bestv || (v == bestv && idx < besti)) { bestv = v; besti = idx; }
    }

    // --- Epilogue: quantized write, loss, codes, segment sums
    const float4* er = (const float4*)(emb + (size_t)besti * DD);
    float* oq = out + OFF_Q + (size_t)b * (DD * TT) + t;
    float* dwp = g_dw + (size_t)besti * DD;
    float lsum = 0.0f;
    #pragma unroll
    for (int j = 0; j < 16; ++j) {
        float4 e4 = __ldg(er + j);
        float x0 = xr[4 * j + 0], x1 = xr[4 * j + 1];
        float x2 = xr[4 * j + 2], x3 = xr[4 * j + 3];
        oq[(size_t)(4 * j + 0) * TT] = e4.x;
        oq[(size_t)(4 * j + 1) * TT] = e4.y;
        oq[(size_t)(4 * j + 2) * TT] = e4.z;
        oq[(size_t)(4 * j + 3) * TT] = e4.w;
        float q0 = e4.x - x0, q1 = e4.y - x1, q2 = e4.z - x2, q3 = e4.w - x3;
        lsum += q0 * q0 + q1 * q1 + q2 * q2 + q3 * q3;
        asm volatile("red.global.add.v4.f32 [%0], {%1,%2,%3,%4};"
                     :: "l"(dwp + 4 * j), "f"(x0), "f"(x1), "f"(x2), "f"(x3) : "memory");
    }
    out[OFF_CODES + n] = (float)besti;
    atomicAdd(&g_counts[besti], 1.0f);

    #pragma unroll
    for (int o = 16; o; o >>= 1) lsum += __shfl_xor_sync(0xffffffffu, lsum, o);
    if (lane == 0) swr[wid] = lsum;
    __syncthreads();
    if (tid == 0)
        atomicAdd(&g_loss, swr[0] + swr[1] + swr[2] + swr[3]);
}

// ---------------------------------------------------------------------------
// Finalize 1: new_cs, cluster-size normalization, loss
// ---------------------------------------------------------------------------
__global__ __launch_bounds__(1024) void vq_fin1(
        const float* __restrict__ ema_cs, float* __restrict__ out) {
    __shared__ float sw[32];
    __shared__ float snv;
    int k = threadIdx.x;
    float cs = DECAYF * ema_cs[k] + OMD * g_counts[k];
    out[OFF_NEWCS + k] = cs;

    float v = cs;
    #pragma unroll
    for (int o = 16; o; o >>= 1) v += __shfl_xor_sync(0xffffffffu, v, o);
    if ((k & 31) == 0) sw[k >> 5] = v;
    __syncthreads();
    if (k < 32) {
        float u = sw[k];
        #pragma unroll
        for (int o = 16; o; o >>= 1) u += __shfl_xor_sync(0xffffffffu, u, o);
        if (k == 0) snv = u;
    }
    __syncthreads();
    float nsum = snv;
    float cluster = (cs + EPSF) / (nsum + (float)KC * EPSF) * nsum;
    g_invcs[k] = 1.0f / cluster;
    if (k == 0) out[OFF_LOSS] = COMMITF * g_loss * (1.0f / (float)QE);
}

// ---------------------------------------------------------------------------
// Finalize 2: new_w, new_embedding
// ---------------------------------------------------------------------------
__global__ __launch_bounds__(256) void vq_fin2(
        const float* __restrict__ ema_w, float* __restrict__ out) {
    int i = blockIdx.x * 256 + threadIdx.x;
    float nw = DECAYF * ema_w[i] + OMD * g_dw[i];
    out[OFF_NEWW + i] = nw;
    out[OFF_NEWEMB + i] = nw * g_invcs[i >> 6];
}

// ---------------------------------------------------------------------------
extern "C" void kernel_launch(void* const* d_in, const int* in_sizes, int n_in,
                              void* d_out, int out_size) {
    const float* z      = (const float*)d_in[0];
    const float* emb    = (const float*)d_in[1];
    const float* ema_cs = (const float*)d_in[2];
    const float* ema_w  = (const float*)d_in[3];
    float* out = (float*)d_out;

    cudaFuncSetAttribute(vq_main_mma, cudaFuncAttributeMaxDynamicSharedMemorySize, SM_TOTAL);

    vq_prep<<<256, 256>>>(emb);
    vq_main_mma<<<512, 128, SM_TOTAL>>>(z, emb, out);
    vq_fin1<<<1, 1024>>>(ema_cs, out);
    vq_fin2<<<256, 256>>>(ema_w, out);
}